// round 1
// baseline (speedup 1.0000x reference)
#include <cuda_runtime.h>

// Problem constants
#define NS   65536
#define KEXP 8
#define DIN  74
#define WID  64
#define DOUT 32
#define TILE 256
#define NT   256
#define MAXTILES (NS / TILE + KEXP)

// smem: Xs[74][256] (reused as layer1 out [64][256]) + Hs[64][256] + Wb(74*64+64) + sids[256]
#define SMEM_FLOATS (DIN * TILE + WID * TILE + DIN * WID + WID)
#define SMEM_BYTES  (SMEM_FLOATS * 4 + TILE * 4)

typedef unsigned long long u64;

// ---------------- device scratch (no allocations allowed) ----------------
__device__ int g_hist[KEXP];
__device__ int g_offs[KEXP + 1];
__device__ int g_cursor[KEXP];
__device__ int g_order[NS];

// ---------------- packed fp32x2 helpers (sm_103a) ----------------
__device__ __forceinline__ u64 pk2(float x, float y) {
    u64 r; asm("mov.b64 %0, {%1, %2};" : "=l"(r) : "f"(x), "f"(y)); return r;
}
__device__ __forceinline__ void upk2(u64 p, float& x, float& y) {
    asm("mov.b64 {%0, %1}, %2;" : "=f"(x), "=f"(y) : "l"(p));
}
__device__ __forceinline__ void fma2(u64& c, u64 a, u64 b) {
    asm("fma.rn.f32x2 %0, %1, %2, %0;" : "+l"(c) : "l"(a), "l"(b));
}

// ---------------- bucketing kernels ----------------
__global__ void k_init() {
    if (threadIdx.x < KEXP) g_hist[threadIdx.x] = 0;
}

__global__ void k_hist(const int* __restrict__ idxs) {
    __shared__ int sh[KEXP];
    if (threadIdx.x < KEXP) sh[threadIdx.x] = 0;
    __syncthreads();
    for (int i = blockIdx.x * blockDim.x + threadIdx.x; i < NS; i += gridDim.x * blockDim.x)
        atomicAdd(&sh[idxs[i]], 1);
    __syncthreads();
    if (threadIdx.x < KEXP) atomicAdd(&g_hist[threadIdx.x], sh[threadIdx.x]);
}

__global__ void k_scan() {
    int acc = 0;
    for (int e = 0; e < KEXP; e++) { g_offs[e] = acc; g_cursor[e] = acc; acc += g_hist[e]; }
    g_offs[KEXP] = acc;
}

// 64 blocks x 1024 contiguous samples each; block-local ranks via smem atomics,
// single global atomicAdd per (block, expert) to claim the range.
__global__ void k_scatter(const int* __restrict__ idxs) {
    __shared__ int s_loc[KEXP];
    __shared__ int s_base[KEXP];
    const int CH = 1024;
    int b0 = blockIdx.x * CH;
    if (threadIdx.x < KEXP) s_loc[threadIdx.x] = 0;
    __syncthreads();
    int e[4], r[4];
#pragma unroll
    for (int j = 0; j < 4; j++) {
        int i = b0 + j * NT + threadIdx.x;
        e[j] = idxs[i];
        r[j] = atomicAdd(&s_loc[e[j]], 1);
    }
    __syncthreads();
    if (threadIdx.x < KEXP)
        s_base[threadIdx.x] = atomicAdd(&g_cursor[threadIdx.x], s_loc[threadIdx.x]);
    __syncthreads();
#pragma unroll
    for (int j = 0; j < 4; j++) {
        int i = b0 + j * NT + threadIdx.x;
        g_order[s_base[e[j]] + r[j]] = i;
    }
}

// ---------------- cooperative weight copy ----------------
__device__ __forceinline__ void copy_w(float* __restrict__ dst, const float* __restrict__ w,
                                       int nw4, const float* __restrict__ bias, int nb4, int tid) {
    float4* d4 = (float4*)dst;
    const float4* s4 = (const float4*)w;
    const float4* b4 = (const float4*)bias;
    for (int j = tid; j < nw4 + nb4; j += NT)
        d4[j] = (j < nw4) ? s4[j] : b4[j - nw4];
}

// ---------------- GEMM: [256 x KD] @ [KD x 64] + bias, relu -> O[64][256] ----------------
template <int KD>
__device__ __forceinline__ void gemm_relu(const float* __restrict__ A,   // [KD][256] k-major
                                          const float* __restrict__ W,   // [KD][64]
                                          const float* __restrict__ bias,
                                          float* __restrict__ O,         // [64][256]
                                          int lane, int cg) {
    u64 acc[8][4];
    const int c0 = cg * 8;
#pragma unroll
    for (int jj = 0; jj < 4; jj++) {
        u64 b = pk2(bias[c0 + 2 * jj], bias[c0 + 2 * jj + 1]);
#pragma unroll
        for (int i = 0; i < 8; i++) acc[i][jj] = b;
    }
#pragma unroll 2
    for (int k = 0; k < KD; k++) {
        float4 a0 = *(const float4*)&A[k * TILE + lane * 8];
        float4 a1 = *(const float4*)&A[k * TILE + lane * 8 + 4];
        float4 w0 = *(const float4*)&W[k * WID + c0];
        float4 w1 = *(const float4*)&W[k * WID + c0 + 4];
        u64 B[4] = { pk2(w0.x, w0.y), pk2(w0.z, w0.w), pk2(w1.x, w1.y), pk2(w1.z, w1.w) };
        float av[8] = { a0.x, a0.y, a0.z, a0.w, a1.x, a1.y, a1.z, a1.w };
#pragma unroll
        for (int i = 0; i < 8; i++) {
            u64 a2 = pk2(av[i], av[i]);
#pragma unroll
            for (int jj = 0; jj < 4; jj++) fma2(acc[i][jj], a2, B[jj]);
        }
    }
#pragma unroll
    for (int jj = 0; jj < 4; jj++) {
        float v0[8], v1[8];
#pragma unroll
        for (int i = 0; i < 8; i++) {
            upk2(acc[i][jj], v0[i], v1[i]);
            v0[i] = fmaxf(v0[i], 0.0f);
            v1[i] = fmaxf(v1[i], 0.0f);
        }
        int cc = c0 + 2 * jj;
        *(float4*)&O[cc * TILE + lane * 8]       = make_float4(v0[0], v0[1], v0[2], v0[3]);
        *(float4*)&O[cc * TILE + lane * 8 + 4]   = make_float4(v0[4], v0[5], v0[6], v0[7]);
        *(float4*)&O[(cc + 1) * TILE + lane * 8]     = make_float4(v1[0], v1[1], v1[2], v1[3]);
        *(float4*)&O[(cc + 1) * TILE + lane * 8 + 4] = make_float4(v1[4], v1[5], v1[6], v1[7]);
    }
}

// ---------------- final layer: [256 x 64] @ [64 x 32] + bias -> global out ----------------
__device__ __forceinline__ void gemm_out(const float* __restrict__ A, const float* __restrict__ W,
                                         const float* __restrict__ bias, float* __restrict__ out,
                                         const int* __restrict__ sids, int cnt, int lane, int cg) {
    u64 acc[8][2];
    const int c0 = cg * 4;
#pragma unroll
    for (int jj = 0; jj < 2; jj++) {
        u64 b = pk2(bias[c0 + 2 * jj], bias[c0 + 2 * jj + 1]);
#pragma unroll
        for (int i = 0; i < 8; i++) acc[i][jj] = b;
    }
#pragma unroll 2
    for (int k = 0; k < WID; k++) {
        float4 a0 = *(const float4*)&A[k * TILE + lane * 8];
        float4 a1 = *(const float4*)&A[k * TILE + lane * 8 + 4];
        float4 w = *(const float4*)&W[k * DOUT + c0];
        u64 B0 = pk2(w.x, w.y), B1 = pk2(w.z, w.w);
        float av[8] = { a0.x, a0.y, a0.z, a0.w, a1.x, a1.y, a1.z, a1.w };
#pragma unroll
        for (int i = 0; i < 8; i++) {
            u64 a2 = pk2(av[i], av[i]);
            fma2(acc[i][0], a2, B0);
            fma2(acc[i][1], a2, B1);
        }
    }
#pragma unroll
    for (int i = 0; i < 8; i++) {
        int row = lane * 8 + i;
        if (row < cnt) {
            float x0, x1, x2, x3;
            upk2(acc[i][0], x0, x1);
            upk2(acc[i][1], x2, x3);
            *(float4*)&out[(size_t)sids[row] * DOUT + c0] = make_float4(x0, x1, x2, x3);
        }
    }
}

// ---------------- fused MLP kernel: one block = (expert, 256-sample tile) ----------------
__global__ void __launch_bounds__(NT) k_mlp(
    const float* __restrict__ positions, const float* __restrict__ viewdirs,
    const float* __restrict__ features,
    const float* __restrict__ W0, const float* __restrict__ b0,
    const float* __restrict__ W1, const float* __restrict__ b1,
    const float* __restrict__ W2, const float* __restrict__ b2,
    float* __restrict__ out) {
    extern __shared__ float sm[];
    float* Xs = sm;                          // [74][256], reused as layer-1 output [64][256]
    float* Hs = sm + DIN * TILE;             // [64][256]
    float* Wb = Hs + WID * TILE;             // weights + bias staging
    int* sids = (int*)(Wb + DIN * WID + WID);
    int tid = threadIdx.x;

    // map blockIdx -> (expert, local tile)
    int e = -1, lt = 0;
    {
        int b = blockIdx.x, acc = 0;
#pragma unroll
        for (int i = 0; i < KEXP; i++) {
            int tiles = (g_offs[i + 1] - g_offs[i] + TILE - 1) / TILE;
            if (e < 0 && b < acc + tiles) { e = i; lt = b - acc; }
            acc += tiles;
        }
    }
    if (e < 0) return;
    int base = g_offs[e] + lt * TILE;
    int cnt = min(TILE, g_offs[e + 1] - base);

    int n = g_order[base + min(tid, cnt - 1)];   // pad partial tiles with a valid row (no write later)
    sids[tid] = n;

    // ---- gather + encode row `tid` into Xs (k-major) ----
    const float4* f4 = (const float4*)(features + (size_t)n * 32);
#pragma unroll
    for (int i = 0; i < 8; i++) {
        float4 f = f4[i];
        Xs[(i * 4 + 0) * TILE + tid] = f.x;
        Xs[(i * 4 + 1) * TILE + tid] = f.y;
        Xs[(i * 4 + 2) * TILE + tid] = f.z;
        Xs[(i * 4 + 3) * TILE + tid] = f.w;
    }
    {
        float p0 = positions[n * 3], p1 = positions[n * 3 + 1], p2 = positions[n * 3 + 2];
        Xs[32 * TILE + tid] = p0; Xs[33 * TILE + tid] = p1; Xs[34 * TILE + tid] = p2;
#pragma unroll
        for (int s = 0; s < 2; s++) {
            float sc = (float)(1 << s);
            float v0 = p0 * sc, v1 = p1 * sc, v2 = p2 * sc;
            Xs[(35 + s * 3) * TILE + tid] = __sinf(v0);
            Xs[(36 + s * 3) * TILE + tid] = __sinf(v1);
            Xs[(37 + s * 3) * TILE + tid] = __sinf(v2);
            Xs[(41 + s * 3) * TILE + tid] = __cosf(v0);
            Xs[(42 + s * 3) * TILE + tid] = __cosf(v1);
            Xs[(43 + s * 3) * TILE + tid] = __cosf(v2);
        }
        float q0 = viewdirs[n * 3], q1 = viewdirs[n * 3 + 1], q2 = viewdirs[n * 3 + 2];
        Xs[47 * TILE + tid] = q0; Xs[48 * TILE + tid] = q1; Xs[49 * TILE + tid] = q2;
#pragma unroll
        for (int s = 0; s < 4; s++) {
            float sc = (float)(1 << s);
            float v0 = q0 * sc, v1 = q1 * sc, v2 = q2 * sc;
            Xs[(50 + s * 3) * TILE + tid] = __sinf(v0);
            Xs[(51 + s * 3) * TILE + tid] = __sinf(v1);
            Xs[(52 + s * 3) * TILE + tid] = __sinf(v2);
            Xs[(62 + s * 3) * TILE + tid] = __cosf(v0);
            Xs[(63 + s * 3) * TILE + tid] = __cosf(v1);
            Xs[(64 + s * 3) * TILE + tid] = __cosf(v2);
        }
    }
    copy_w(Wb, W0 + e * DIN * WID, (DIN * WID) / 4, b0 + e * WID, WID / 4, tid);
    __syncthreads();

    int lane = tid & 31, cg = tid >> 5;
    gemm_relu<DIN>(Xs, Wb, Wb + DIN * WID, Hs, lane, cg);
    __syncthreads();

    copy_w(Wb, W1 + e * WID * WID, (WID * WID) / 4, b1 + e * WID, WID / 4, tid);
    __syncthreads();
    gemm_relu<WID>(Hs, Wb, Wb + WID * WID, Xs, lane, cg);
    __syncthreads();

    copy_w(Wb, W2 + e * WID * DOUT, (WID * DOUT) / 4, b2 + e * DOUT, DOUT / 4, tid);
    __syncthreads();
    gemm_out(Xs, Wb, Wb + WID * DOUT, out, sids, cnt, lane, cg);
}

// ---------------- launch ----------------
extern "C" void kernel_launch(void* const* d_in, const int* in_sizes, int n_in,
                              void* d_out, int out_size) {
    (void)in_sizes; (void)n_in; (void)out_size;
    const int*   idxs      = (const int*)d_in[0];
    const float* positions = (const float*)d_in[1];
    const float* viewdirs  = (const float*)d_in[2];
    const float* features  = (const float*)d_in[3];
    const float* W0 = (const float*)d_in[4];
    const float* b0 = (const float*)d_in[5];
    const float* W1 = (const float*)d_in[6];
    const float* b1 = (const float*)d_in[7];
    const float* W2 = (const float*)d_in[8];
    const float* b2 = (const float*)d_in[9];
    float* out = (float*)d_out;

    // idempotent, non-stream API: executes at capture time, persists for replays
    cudaFuncSetAttribute(k_mlp, cudaFuncAttributeMaxDynamicSharedMemorySize, SMEM_BYTES);

    k_init<<<1, 32>>>();
    k_hist<<<64, NT>>>(idxs);
    k_scan<<<1, 1>>>();
    k_scatter<<<64, NT>>>(idxs);
    k_mlp<<<MAXTILES, NT, SMEM_BYTES>>>(positions, viewdirs, features,
                                        W0, b0, W1, b1, W2, b2, out);
}